// round 16
// baseline (speedup 1.0000x reference)
#include <cuda_runtime.h>
#include <cuda_bf16.h>
#include <cstdint>

#define NA 60000
#define NBOND 120000
#define MAXNB 6
#define HID 512
#define AF 133
#define BF 147
#define NM 512

#define KP_WI 160    // 32k-multiple
#define KP_WH 512
#define KP_WO 672    // padded to 32k-multiple (645 -> 672)

// ---------------- scratch (device globals) -----------------------------------
__device__ float g_inp[(size_t)NBOND * HID];
__device__ float g_msgA[(size_t)NBOND * HID];
__device__ float g_msgB[(size_t)NBOND * HID];
__device__ float g_amsg[(size_t)NA * HID];
__device__ float g_ah[(size_t)NA * HID];
__device__ float g_sums[NM * HID];
__device__ float g_cnt[NM];
__device__ int   g_a2b[NA * MAXNB];
__device__ int   g_b2a[NBOND];
__device__ int   g_b2revb[NBOND];
__device__ int   g_mol[NA];
__device__ int   g_any32[4];
__device__ unsigned short g_Wi2[512 * KP_WI * 2];
__device__ unsigned short g_Wh2[512 * KP_WH * 2];
__device__ unsigned short g_Wo2[512 * KP_WO * 2];
__device__ unsigned short g_pA[(size_t)NA * KP_WO * 2];

// ---------------- helpers -----------------------------------------------------
__device__ __forceinline__ uint32_t smem_u32(const void* p) {
    uint32_t a;
    asm("{ .reg .u64 t; cvta.to.shared.u64 t, %1; cvt.u32.u64 %0, t; }" : "=r"(a) : "l"(p));
    return a;
}
__device__ __forceinline__ void ldm_x4(uint32_t* r, uint32_t addr) {
    asm volatile("ldmatrix.sync.aligned.m8n8.x4.shared.b16 {%0,%1,%2,%3}, [%4];"
                 : "=r"(r[0]), "=r"(r[1]), "=r"(r[2]), "=r"(r[3]) : "r"(addr));
}
__device__ __forceinline__ void mma_bf16(float* c, const uint32_t* a, uint32_t b0, uint32_t b1) {
    asm volatile("mma.sync.aligned.m16n8k16.row.col.f32.bf16.bf16.f32 "
                 "{%0,%1,%2,%3}, {%4,%5,%6,%7}, {%8,%9}, {%0,%1,%2,%3};"
                 : "+f"(c[0]), "+f"(c[1]), "+f"(c[2]), "+f"(c[3])
                 : "r"(a[0]), "r"(a[1]), "r"(a[2]), "r"(a[3]), "r"(b0), "r"(b1));
}
__device__ __forceinline__ void cp16(uint32_t dst, const void* src, int valid) {
    int sz = valid ? 16 : 0;
    asm volatile("cp.async.cg.shared.global [%0], [%1], 16, %2;"
                 :: "r"(dst), "l"(src), "r"(sz) : "memory");
}
__device__ __forceinline__ uint32_t pack2(float a, float b) {
    __nv_bfloat16 ha = __float2bfloat16(a), hb = __float2bfloat16(b);
    return (uint32_t)__bfloat16_as_ushort(ha) | ((uint32_t)__bfloat16_as_ushort(hb) << 16);
}

// ---------------- merged index scan / convert --------------------------------
#define N0 (NA * MAXNB)
#define N1 NBOND
#define N2 NBOND
#define N3 NA
#define NTOT (N0 + N1 + N2 + N3)

__global__ void scan_all_kernel(const unsigned* a2b, const unsigned* b2a,
                                const unsigned* b2revb, const unsigned* mol) {
    int idx = blockIdx.x * blockDim.x + threadIdx.x;
    if (idx >= NTOT) return;
    const unsigned* p; int i, fi;
    if (idx < N0)                { p = a2b;    i = idx;             fi = 0; }
    else if (idx < N0 + N1)      { p = b2a;    i = idx - N0;        fi = 1; }
    else if (idx < N0 + N1 + N2) { p = b2revb; i = idx - N0 - N1;   fi = 2; }
    else                         { p = mol;    i = idx - N0 - N1 - N2; fi = 3; }
    if ((i & 1) && p[i] != 0u) atomicOr(&g_any32[fi], 1);
}

__global__ void convert_all_kernel(const void* a2b, const void* b2a,
                                   const void* b2revb, const void* mol) {
    int idx = blockIdx.x * blockDim.x + threadIdx.x;
    if (idx >= NTOT) return;
    const void* p; int i, fi; int* dst;
    if (idx < N0)                { p = a2b;    i = idx;                fi = 0; dst = g_a2b; }
    else if (idx < N0 + N1)      { p = b2a;    i = idx - N0;           fi = 1; dst = g_b2a; }
    else if (idx < N0 + N1 + N2) { p = b2revb; i = idx - N0 - N1;      fi = 2; dst = g_b2revb; }
    else                         { p = mol;    i = idx - N0 - N1 - N2; fi = 3; dst = g_mol; }
    if (g_any32[fi]) dst[i] = ((const int*)p)[i];
    else             dst[i] = (int)((const long long*)p)[i];
}

// ---------------- element workers ---------------------------------------------
__device__ __forceinline__ void conv_w_elem(const float* __restrict__ W,
                                            unsigned short* __restrict__ Wp,
                                            int K, int KP, int idx) {
    int n = idx / KP, k = idx - n * KP;
    float v = (k < K) ? W[(size_t)n * K + k] : 0.f;
    __nv_bfloat16 hb = __float2bfloat16(v);
    float r = v - __bfloat162float(hb);
    __nv_bfloat16 lb = __float2bfloat16(r);
    size_t base = (size_t)n * KP * 2 + (size_t)(k >> 4) * 32 + (k & 15);
    Wp[base]      = __bfloat16_as_ushort(hb);
    Wp[base + 16] = __bfloat16_as_ushort(lb);
}

__device__ __forceinline__ void pack_row8(const float v[8], unsigned short* out,
                                          int KP, int row, int kb) {
    float lo[8];
    #pragma unroll
    for (int e = 0; e < 8; e++)
        lo[e] = v[e] - __bfloat162float(__float2bfloat16(v[e]));
    uint4 hq = make_uint4(pack2(v[0], v[1]), pack2(v[2], v[3]), pack2(v[4], v[5]), pack2(v[6], v[7]));
    uint4 lq = make_uint4(pack2(lo[0], lo[1]), pack2(lo[2], lo[3]), pack2(lo[4], lo[5]), pack2(lo[6], lo[7]));
    int c = kb >> 4, c2 = (kb >> 3) & 1;
    char* rb_ = (char*)(out + (size_t)row * KP * 2) + c * 64 + c2 * 16;
    *(uint4*)(rb_)      = hq;
    *(uint4*)(rb_ + 32) = lq;
}

// ---------------- prep: weight packs + W_i A pack ----------------------------
#define NWI (512 * KP_WI)
#define NWH (512 * KP_WH)
#define NWO (512 * KP_WO)
#define NPK (NBOND * (KP_WI / 8))
#define NPREP (NWI + NWH + NWO + NPK)

__global__ void prep_kernel(const float* __restrict__ Wi, const float* __restrict__ Wh,
                            const float* __restrict__ Wo, const float* __restrict__ f_bonds) {
    int idx = blockIdx.x * blockDim.x + threadIdx.x;
    if (idx >= NPREP) return;
    if (idx < NWI) { conv_w_elem(Wi, g_Wi2, BF, KP_WI, idx); return; }
    idx -= NWI;
    if (idx < NWH) { conv_w_elem(Wh, g_Wh2, HID, KP_WH, idx); return; }
    idx -= NWH;
    if (idx < NWO) { conv_w_elem(Wo, g_Wo2, AF + HID, KP_WO, idx); return; }
    idx -= NWO;
    const int t8n = KP_WI / 8;
    int row = idx / t8n;
    int kb = (idx - row * t8n) * 8;
    float v[8];
    const float* r = f_bonds + (size_t)row * BF;
    #pragma unroll
    for (int e = 0; e < 8; e++)
        v[e] = (kb + e < BF) ? r[kb + e] : 0.f;
    pack_row8(v, g_pA, KP_WI, row, kb);
}

// ---------------- W_o A pack (concat f_atoms | amsg) -------------------------
__global__ void pack_awo_kernel(const float* __restrict__ f_atoms,
                                const float* __restrict__ amsg) {
    const int t8n = KP_WO / 8;
    int idx = blockIdx.x * blockDim.x + threadIdx.x;
    if (idx >= NA * t8n) return;
    int row = idx / t8n;
    int kb = (idx - row * t8n) * 8;
    float v[8];
    #pragma unroll
    for (int e = 0; e < 8; e++) {
        int k = kb + e;
        float x = 0.f;
        if (k < AF) x = f_atoms[(size_t)row * AF + k];
        else if (k < AF + HID) x = amsg[(size_t)row * HID + (k - AF)];
        v[e] = x;
    }
    pack_row8(v, g_pA, KP_WO, row, kb);
}

// ---------------- geometry ----------------------------------------------------
// packed GEMM (512 thr): 128M x 256N, 32-k chunks
#define ROWB2 144                     // 128B data (two 16k segs) + 16B pad
#define A_ST2 (128 * ROWB2)           // 18432
#define B_ST2 (256 * ROWB2)           // 36864
#define SMEM_W (3 * (A_ST2 + B_ST2))  // 165888
// fused GEMM (256 thr): 128M x 128N, 16-k chunks (R9-proven)
#define ROWB 80
#define BUFB (128 * ROWB)             // 10240
#define FSM_BYTES (6 * BUFB)          // 61440

// ------- packed-A GEMM (W_i / W_o): 512 thr, 16 warps 64x32, 32k chunks -----
__global__ __launch_bounds__(512, 1)
void mma_gemm_kernel(const unsigned short* __restrict__ pA,
                     const unsigned short* __restrict__ Wp, int KP, int NC2,
                     const float* __restrict__ bias,
                     float* __restrict__ out1, int relu1, int M) {
    extern __shared__ char dyn[];
    const uint32_t aBase = smem_u32(dyn);
    const uint32_t bBase = aBase + 3 * A_ST2;

    const int tid = threadIdx.x;
    const int wid = tid >> 5, lane = tid & 31;
    const int bm = blockIdx.y * 128;
    const int bn = blockIdx.x * 256;
    const int wm = (wid >> 3) * 64;
    const int wn = (wid & 7) * 32;

    const int rA = tid >> 2, qA = tid & 3;
    const int gmL = bm + rA;
    const int okA = gmL < M;
    const int gmc = okA ? gmL : (M - 1);
    const char* gA = (const char*)(pA + (size_t)gmc * KP * 2) + qA * 32;
    const uint32_t sA = aBase + rA * ROWB2 + qA * 32;
    const int rB = tid >> 1, hB = tid & 1;
    const char* gB = (const char*)(Wp + (size_t)(bn + rB) * KP * 2) + hB * 64;
    const uint32_t sB = bBase + rB * ROWB2 + hB * 64;

    float acc[4][4][4];
    #pragma unroll
    for (int i = 0; i < 4; i++)
        #pragma unroll
        for (int j = 0; j < 4; j++)
            #pragma unroll
            for (int e = 0; e < 4; e++) acc[i][j][e] = 0.f;

    auto prefetch = [&](int c, int s) {
        const char* a = gA + (size_t)c * 128;
        cp16(sA + s * A_ST2, a, okA);
        cp16(sA + s * A_ST2 + 16, a + 16, okA);
        const char* b = gB + (size_t)c * 128;
        cp16(sB + s * B_ST2, b, 1);
        cp16(sB + s * B_ST2 + 16, b + 16, 1);
        cp16(sB + s * B_ST2 + 32, b + 32, 1);
        cp16(sB + s * B_ST2 + 48, b + 48, 1);
        asm volatile("cp.async.commit_group;" ::: "memory");
    };

    const uint32_t aAddr = aBase + (wm + (lane & 15)) * ROWB2 + (lane >> 4) * 16;
    const uint32_t bAddr = bBase + (wn + (lane & 7) + (lane >= 16 ? 8 : 0)) * ROWB2
                                 + ((lane >> 3) & 1) * 16;

    prefetch(0, 0);
    prefetch(1, 1);
    for (int c = 0; c < NC2; c++) {
        int s = c % 3;
        if (c + 1 < NC2) { asm volatile("cp.async.wait_group 1;" ::: "memory"); }
        else             { asm volatile("cp.async.wait_group 0;" ::: "memory"); }
        __syncthreads();
        if (c + 2 < NC2) prefetch(c + 2, (c + 2) % 3);

        #pragma unroll
        for (int sub = 0; sub < 2; sub++) {
            uint32_t aH[4][4], aL[4][4], bH[2][4], bL[2][4];
            const uint32_t ao = s * A_ST2 + sub * 64;
            const uint32_t bo = s * B_ST2 + sub * 64;
            #pragma unroll
            for (int i = 0; i < 4; i++) {
                ldm_x4(aH[i], aAddr + ao + i * 16 * ROWB2);
                ldm_x4(aL[i], aAddr + ao + i * 16 * ROWB2 + 32);
            }
            #pragma unroll
            for (int p = 0; p < 2; p++) {
                ldm_x4(bH[p], bAddr + bo + p * 16 * ROWB2);
                ldm_x4(bL[p], bAddr + bo + p * 16 * ROWB2 + 32);
            }
            #pragma unroll
            for (int i = 0; i < 4; i++)
                #pragma unroll
                for (int j = 0; j < 4; j++) {
                    mma_bf16(acc[i][j], aH[i], bH[j >> 1][(j & 1) * 2], bH[j >> 1][(j & 1) * 2 + 1]);
                    mma_bf16(acc[i][j], aL[i], bH[j >> 1][(j & 1) * 2], bH[j >> 1][(j & 1) * 2 + 1]);
                    mma_bf16(acc[i][j], aH[i], bL[j >> 1][(j & 1) * 2], bL[j >> 1][(j & 1) * 2 + 1]);
                }
        }
    }

    const int g = lane >> 2, tg = lane & 3;
    #pragma unroll
    for (int i = 0; i < 4; i++) {
        #pragma unroll
        for (int h = 0; h < 2; h++) {
            int gm = bm + wm + i * 16 + g + h * 8;
            if (gm >= M) continue;
            #pragma unroll
            for (int j = 0; j < 4; j++) {
                int gn = bn + wn + j * 8 + tg * 2;
                float v0 = acc[i][j][h * 2 + 0];
                float v1 = acc[i][j][h * 2 + 1];
                if (bias) {
                    float2 b = *(const float2*)(bias + gn);
                    v0 += b.x; v1 += b.y;
                }
                float2 o = relu1 ? make_float2(fmaxf(v0, 0.f), fmaxf(v1, 0.f))
                                 : make_float2(v0, v1);
                *(float2*)(out1 + (size_t)gm * HID + gn) = o;
            }
        }
    }
}

// ------- fused W_h GEMM (R9-proven): 256 thr, 128x128, 3-stage, 1 sync ------
__global__ __launch_bounds__(256, 2)
void mma_gemm_fused_kernel(const float* __restrict__ amsg,
                           const float* __restrict__ msg,
                           const int* __restrict__ b2a,
                           const int* __restrict__ b2revb,
                           const unsigned short* __restrict__ Wp,
                           const float* __restrict__ inp,
                           float* __restrict__ out1, int reluMsg) {
    const int NC = KP_WH / 16;   // 32
    extern __shared__ char dyn[];
    const uint32_t aBase = smem_u32(dyn);
    const uint32_t bBase = aBase + 3 * BUFB;

    const int tid = threadIdx.x;
    const int wid = tid >> 5, lane = tid & 31;
    const int bm = blockIdx.y * 128;
    const int bn = blockIdx.x * 128;
    const int wm = (wid >> 2) * 64;
    const int wn = (wid & 3) * 32;

    const int rL = tid >> 1;
    const int c2 = tid & 1;
    const int gmL = bm + rL;
    const int okA = gmL < NBOND;
    const int gmc = okA ? gmL : (NBOND - 1);
    const int sa = b2a[gmc];
    const int rb = b2revb[gmc];
    const char* gU = (const char*)(amsg + (size_t)sa * HID) + c2 * 32;
    const char* gW = (const char*)(msg + (size_t)rb * HID) + c2 * 32;
    const char* gB = (const char*)(Wp + (size_t)(bn + rL) * KP_WH * 2) + c2 * 32;
    const uint32_t sB = bBase + rL * ROWB + c2 * 32;

    float acc[4][4][4];
    #pragma unroll
    for (int i = 0; i < 4; i++)
        #pragma unroll
        for (int j = 0; j < 4; j++)
            #pragma unroll
            for (int e = 0; e < 4; e++) acc[i][j][e] = 0.f;

    float4 u0, u1, w0, w1;
    auto loadA_issue = [&](int c) {
        const char* u = gU + (size_t)c * 64;
        const char* w = gW + (size_t)c * 64;
        u0 = *(const float4*)(u);
        u1 = *(const float4*)(u + 16);
        w0 = *(const float4*)(w);
        w1 = *(const float4*)(w + 16);
    };
    auto storeA = [&](int s) {
        float4 ww0 = w0, ww1 = w1;
        if (reluMsg) {
            ww0.x = fmaxf(ww0.x, 0.f); ww0.y = fmaxf(ww0.y, 0.f);
            ww0.z = fmaxf(ww0.z, 0.f); ww0.w = fmaxf(ww0.w, 0.f);
            ww1.x = fmaxf(ww1.x, 0.f); ww1.y = fmaxf(ww1.y, 0.f);
            ww1.z = fmaxf(ww1.z, 0.f); ww1.w = fmaxf(ww1.w, 0.f);
        }
        float v[8];
        v[0] = u0.x - ww0.x; v[1] = u0.y - ww0.y; v[2] = u0.z - ww0.z; v[3] = u0.w - ww0.w;
        v[4] = u1.x - ww1.x; v[5] = u1.y - ww1.y; v[6] = u1.z - ww1.z; v[7] = u1.w - ww1.w;
        float lo[8];
        #pragma unroll
        for (int e = 0; e < 8; e++)
            lo[e] = v[e] - __bfloat162float(__float2bfloat16(v[e]));
        uint4 hq = make_uint4(pack2(v[0], v[1]), pack2(v[2], v[3]), pack2(v[4], v[5]), pack2(v[6], v[7]));
        uint4 lq = make_uint4(pack2(lo[0], lo[1]), pack2(lo[2], lo[3]), pack2(lo[4], lo[5]), pack2(lo[6], lo[7]));
        char* ar = dyn + s * BUFB + rL * ROWB;
        *(uint4*)(ar + c2 * 16)      = hq;
        *(uint4*)(ar + 32 + c2 * 16) = lq;
    };
    auto prefetchB = [&](int c, int s) {
        const char* b = gB + (size_t)c * 64;
        cp16(sB + s * BUFB, b, 1);
        cp16(sB + s * BUFB + 16, b + 16, 1);
        asm volatile("cp.async.commit_group;" ::: "memory");
    };

    const uint32_t aAddr = aBase + (wm + (lane & 15)) * ROWB + (lane >> 4) * 16;
    const uint32_t bAddr = bBase + (wn + (lane & 7) + (lane >= 16 ? 8 : 0)) * ROWB
                                 + ((lane >> 3) & 1) * 16;

    loadA_issue(0); storeA(0); prefetchB(0, 0);
    loadA_issue(1); storeA(1); prefetchB(1, 1);

    int buf = 0;
    #pragma unroll 1
    for (int c = 0; c < NC; c++) {
        if (c + 1 < NC) { asm volatile("cp.async.wait_group 1;" ::: "memory"); }
        else            { asm volatile("cp.async.wait_group 0;" ::: "memory"); }
        __syncthreads();

        int nb = buf + 2; if (nb >= 3) nb -= 3;
        if (c + 2 < NC) loadA_issue(c + 2);

        uint32_t af[4][4], bH[2][4], bL[2][4];
        #pragma unroll
        for (int p = 0; p < 2; p++) {
            ldm_x4(bH[p], bAddr + buf * BUFB + p * 16 * ROWB);
            ldm_x4(bL[p], bAddr + buf * BUFB + p * 16 * ROWB + 32);
        }
        #pragma unroll
        for (int i = 0; i < 4; i++)
            ldm_x4(af[i], aAddr + buf * BUFB + i * 16 * ROWB);        // aH
        #pragma unroll
        for (int i = 0; i < 4; i++)
            #pragma unroll
            for (int j = 0; j < 4; j++) {
                mma_bf16(acc[i][j], af[i], bH[j >> 1][(j & 1) * 2], bH[j >> 1][(j & 1) * 2 + 1]);
                mma_bf16(acc[i][j], af[i], bL[j >> 1][(j & 1) * 2], bL[j >> 1][(j & 1) * 2 + 1]);
            }
        #pragma unroll
        for (int i = 0; i < 4; i++)
            ldm_x4(af[i], aAddr + buf * BUFB + i * 16 * ROWB + 32);   // aL
        #pragma unroll
        for (int i = 0; i < 4; i++)
            #pragma unroll
            for (int j = 0; j < 4; j++)
                mma_bf16(acc[i][j], af[i], bH[j >> 1][(j & 1) * 2], bH[j >> 1][(j & 1) * 2 + 1]);

        if (c + 2 < NC) { storeA(nb); prefetchB(c + 2, nb); }
        buf++; if (buf == 3) buf = 0;
    }

    const int g = lane >> 2, tg = lane & 3;
    #pragma unroll
    for (int i = 0; i < 4; i++) {
        #pragma unroll
        for (int h = 0; h < 2; h++) {
            int gm = bm + wm + i * 16 + g + h * 8;
            if (gm >= NBOND) continue;
            #pragma unroll
            for (int j = 0; j < 4; j++) {
                int gn = bn + wn + j * 8 + tg * 2;
                float2 a = *(const float2*)(inp + (size_t)gm * HID + gn);
                float v0 = acc[i][j][h * 2 + 0] + a.x;
                float v1 = acc[i][j][h * 2 + 1] + a.y;
                *(float2*)(out1 + (size_t)gm * HID + gn) =
                    make_float2(fmaxf(v0, 0.f), fmaxf(v1, 0.f));
            }
        }
    }
}

// ----- gather: warp per atom; lane covers float4 lane, +32, +64, +96 (full row)
__global__ void gather_sum_kernel(const float* __restrict__ msg,
                                  float* __restrict__ amsg, int reluSrc) {
    int gidx = blockIdx.x * blockDim.x + threadIdx.x;
    int a = gidx >> 5;
    int lane = gidx & 31;
    if (a >= NA) return;
    int bidx[MAXNB];
    #pragma unroll
    for (int j = 0; j < MAXNB; j++) bidx[j] = g_a2b[a * MAXNB + j];
    float4 acc[4];
    #pragma unroll
    for (int q = 0; q < 4; q++) acc[q] = make_float4(0.f, 0.f, 0.f, 0.f);
    #pragma unroll
    for (int j = 0; j < MAXNB; j++) {
        const float4* row = (const float4*)(msg + (size_t)bidx[j] * HID);
        #pragma unroll
        for (int q = 0; q < 4; q++) {
            float4 v = row[lane + q * 32];
            if (reluSrc) {
                v.x = fmaxf(v.x, 0.f); v.y = fmaxf(v.y, 0.f);
                v.z = fmaxf(v.z, 0.f); v.w = fmaxf(v.w, 0.f);
            }
            acc[q].x += v.x; acc[q].y += v.y; acc[q].z += v.z; acc[q].w += v.w;
        }
    }
    float4* dst = (float4*)(amsg + (size_t)a * HID);
    #pragma unroll
    for (int q = 0; q < 4; q++) dst[lane + q * 32] = acc[q];
}

// ---------------- pooling -----------------------------------------------------
__global__ void pool_zero_kernel() {
    int i = blockIdx.x * blockDim.x + threadIdx.x;
    if (i < NM * HID) g_sums[i] = 0.f;
    if (i < NM) g_cnt[i] = 0.f;
}
__global__ void pool_sum_kernel(const float* __restrict__ ah) {
    int idx = blockIdx.x * blockDim.x + threadIdx.x;
    const int h4 = HID / 4;
    if (idx >= NA * h4) return;
    int a = idx / h4;
    int h = (idx - a * h4) * 4;
    int m = g_mol[a];
    float4 v = *(const float4*)(ah + (size_t)a * HID + h);
    float* dst = g_sums + (size_t)m * HID + h;
    atomicAdd(dst + 0, v.x);
    atomicAdd(dst + 1, v.y);
    atomicAdd(dst + 2, v.z);
    atomicAdd(dst + 3, v.w);
    if (h == 0) atomicAdd(&g_cnt[m], 1.f);
}
__global__ void finalize_kernel(float* __restrict__ out) {
    int i = blockIdx.x * blockDim.x + threadIdx.x;
    if (i >= NM * HID) return;
    float c = g_cnt[i / HID];
    out[i] = g_sums[i] / fmaxf(c, 1.f);
}

// ---------------- launch ------------------------------------------------------
extern "C" void kernel_launch(void* const* d_in, const int* in_sizes, int n_in,
                              void* d_out, int out_size) {
    const float* f_atoms = (const float*)d_in[0];
    const float* f_bonds = (const float*)d_in[1];
    const float* W_i     = (const float*)d_in[2];
    const float* W_h     = (const float*)d_in[3];
    const float* W_o     = (const float*)d_in[4];
    const float* b_o     = (const float*)d_in[5];
    const void*  a2b     = d_in[6];
    const void*  b2a     = d_in[7];
    const void*  b2revb  = d_in[8];
    const void*  mol     = d_in[9];
    float* out = (float*)d_out;

    int* d_b2a;    cudaGetSymbolAddress((void**)&d_b2a, g_b2a);
    int* d_b2revb; cudaGetSymbolAddress((void**)&d_b2revb, g_b2revb);
    float* d_inp;  cudaGetSymbolAddress((void**)&d_inp, g_inp);
    float* d_msgA; cudaGetSymbolAddress((void**)&d_msgA, g_msgA);
    float* d_msgB; cudaGetSymbolAddress((void**)&d_msgB, g_msgB);
    float* d_amsg; cudaGetSymbolAddress((void**)&d_amsg, g_amsg);
    float* d_ah;   cudaGetSymbolAddress((void**)&d_ah, g_ah);
    unsigned short* d_Wi2; cudaGetSymbolAddress((void**)&d_Wi2, g_Wi2);
    unsigned short* d_Wh2; cudaGetSymbolAddress((void**)&d_Wh2, g_Wh2);
    unsigned short* d_Wo2; cudaGetSymbolAddress((void**)&d_Wo2, g_Wo2);
    unsigned short* d_pA;  cudaGetSymbolAddress((void**)&d_pA, g_pA);

    static int init_done = 0;
    if (!init_done) {
        cudaFuncSetAttribute(mma_gemm_kernel,
                             cudaFuncAttributeMaxDynamicSharedMemorySize, SMEM_W);
        cudaFuncSetAttribute(mma_gemm_fused_kernel,
                             cudaFuncAttributeMaxDynamicSharedMemorySize, FSM_BYTES);
        init_done = 1;
    }

    const int mt_b = (NBOND + 127) / 128;     // 938
    const int mt_a = (NA + 127) / 128;        // 469
    const int gthreads = 256;
    const int gblocks_g = (NA * 32 + gthreads - 1) / gthreads;
    const int gblocks_p = (NA * (HID / 4) + gthreads - 1) / gthreads;

    // setup
    scan_all_kernel<<<(NTOT + 255) / 256, 256>>>(
        (const unsigned*)a2b, (const unsigned*)b2a, (const unsigned*)b2revb, (const unsigned*)mol);
    convert_all_kernel<<<(NTOT + 255) / 256, 256>>>(a2b, b2a, b2revb, mol);
    prep_kernel<<<(NPREP + 255) / 256, 256>>>(W_i, W_h, W_o, f_bonds);

    // inp = f_bonds @ W_i^T (pre-relu; msg0 virtual)
    mma_gemm_kernel<<<dim3(2, mt_b), 512, SMEM_W>>>(
        d_pA, d_Wi2, KP_WI, KP_WI / 32, nullptr, d_inp, 0, NBOND);

    // message passing; it0 applies relu on read
    gather_sum_kernel<<<gblocks_g, gthreads>>>(d_inp, d_amsg, 1);
    mma_gemm_fused_kernel<<<dim3(4, mt_b), 256, FSM_BYTES>>>(
        d_amsg, d_inp, d_b2a, d_b2revb, d_Wh2, d_inp, d_msgA, 1);

    float* cur = d_msgA;
    float* alt = d_msgB;
    for (int it = 1; it < 4; it++) {
        gather_sum_kernel<<<gblocks_g, gthreads>>>(cur, d_amsg, 0);
        mma_gemm_fused_kernel<<<dim3(4, mt_b), 256, FSM_BYTES>>>(
            d_amsg, cur, d_b2a, d_b2revb, d_Wh2, d_inp, alt, 0);
        float* t = cur; cur = alt; alt = t;
    }

    // final gather + W_o GEMM
    gather_sum_kernel<<<gblocks_g, gthreads>>>(cur, d_amsg, 0);
    pack_awo_kernel<<<(NA * (KP_WO / 8) + 255) / 256, 256>>>(f_atoms, d_amsg);
    mma_gemm_kernel<<<dim3(2, mt_a), 512, SMEM_W>>>(
        d_pA, d_Wo2, KP_WO, KP_WO / 32, b_o, d_ah, 1, NA);

    // pooling
    pool_zero_kernel<<<(NM * HID + 255) / 256, 256>>>();
    pool_sum_kernel<<<gblocks_p, gthreads>>>(d_ah);
    finalize_kernel<<<(NM * HID + 255) / 256, 256>>>(out);
}

// round 17
// speedup vs baseline: 1.0929x; 1.0929x over previous
#include <cuda_runtime.h>
#include <cuda_fp16.h>
#include <cstdint>

#define NA 60000
#define NBOND 120000
#define MAXNB 6
#define HID 512
#define AF 133
#define BF 147
#define NM 512

#define KP_WI 160
#define KP_WH 512
#define KP_WO 656

// ---------------- scratch (device globals) -----------------------------------
__device__ float g_inp[(size_t)NBOND * HID];
__device__ float g_msgA[(size_t)NBOND * HID];
__device__ float g_msgB[(size_t)NBOND * HID];
__device__ float g_amsg[(size_t)NA * HID];
__device__ float g_ah[(size_t)NA * HID];
__device__ float g_sums[NM * HID];
__device__ float g_cnt[NM];
__device__ int   g_a2b[NA * MAXNB];
__device__ int   g_b2a[NBOND];
__device__ int   g_b2revb[NBOND];
__device__ int   g_mol[NA];
__device__ int   g_any32[4];
// weights: single fp16 per element, row-major with KP stride
__device__ unsigned short g_Wi2[512 * KP_WI];
__device__ unsigned short g_Wh2[512 * KP_WH];
__device__ unsigned short g_Wo2[512 * KP_WO];
// packed A: fp16 [hi16|lo16] per 16-k chunk
__device__ unsigned short g_pA[(size_t)NA * KP_WO * 2];

// ---------------- helpers -----------------------------------------------------
__device__ __forceinline__ uint32_t smem_u32(const void* p) {
    uint32_t a;
    asm("{ .reg .u64 t; cvta.to.shared.u64 t, %1; cvt.u32.u64 %0, t; }" : "=r"(a) : "l"(p));
    return a;
}
__device__ __forceinline__ void ldm_x4(uint32_t* r, uint32_t addr) {
    asm volatile("ldmatrix.sync.aligned.m8n8.x4.shared.b16 {%0,%1,%2,%3}, [%4];"
                 : "=r"(r[0]), "=r"(r[1]), "=r"(r[2]), "=r"(r[3]) : "r"(addr));
}
__device__ __forceinline__ void mma_f16(float* c, const uint32_t* a, uint32_t b0, uint32_t b1) {
    asm volatile("mma.sync.aligned.m16n8k16.row.col.f32.f16.f16.f32 "
                 "{%0,%1,%2,%3}, {%4,%5,%6,%7}, {%8,%9}, {%0,%1,%2,%3};"
                 : "+f"(c[0]), "+f"(c[1]), "+f"(c[2]), "+f"(c[3])
                 : "r"(a[0]), "r"(a[1]), "r"(a[2]), "r"(a[3]), "r"(b0), "r"(b1));
}
__device__ __forceinline__ void cp16(uint32_t dst, const void* src, int valid) {
    int sz = valid ? 16 : 0;
    asm volatile("cp.async.cg.shared.global [%0], [%1], 16, %2;"
                 :: "r"(dst), "l"(src), "r"(sz) : "memory");
}
__device__ __forceinline__ uint32_t pack2h(float a, float b) {
    __half ha = __float2half_rn(a), hb = __float2half_rn(b);
    return (uint32_t)__half_as_ushort(ha) | ((uint32_t)__half_as_ushort(hb) << 16);
}

// ---------------- merged index scan / convert --------------------------------
#define N0 (NA * MAXNB)
#define N1 NBOND
#define N2 NBOND
#define N3 NA
#define NTOT (N0 + N1 + N2 + N3)

__global__ void scan_all_kernel(const unsigned* a2b, const unsigned* b2a,
                                const unsigned* b2revb, const unsigned* mol) {
    int idx = blockIdx.x * blockDim.x + threadIdx.x;
    if (idx >= NTOT) return;
    const unsigned* p; int i, fi;
    if (idx < N0)                { p = a2b;    i = idx;             fi = 0; }
    else if (idx < N0 + N1)      { p = b2a;    i = idx - N0;        fi = 1; }
    else if (idx < N0 + N1 + N2) { p = b2revb; i = idx - N0 - N1;   fi = 2; }
    else                         { p = mol;    i = idx - N0 - N1 - N2; fi = 3; }
    if ((i & 1) && p[i] != 0u) atomicOr(&g_any32[fi], 1);
}

__global__ void convert_all_kernel(const void* a2b, const void* b2a,
                                   const void* b2revb, const void* mol) {
    int idx = blockIdx.x * blockDim.x + threadIdx.x;
    if (idx >= NTOT) return;
    const void* p; int i, fi; int* dst;
    if (idx < N0)                { p = a2b;    i = idx;                fi = 0; dst = g_a2b; }
    else if (idx < N0 + N1)      { p = b2a;    i = idx - N0;           fi = 1; dst = g_b2a; }
    else if (idx < N0 + N1 + N2) { p = b2revb; i = idx - N0 - N1;      fi = 2; dst = g_b2revb; }
    else                         { p = mol;    i = idx - N0 - N1 - N2; fi = 3; dst = g_mol; }
    if (g_any32[fi]) dst[i] = ((const int*)p)[i];
    else             dst[i] = (int)((const long long*)p)[i];
}

// ---------------- element workers ---------------------------------------------
__device__ __forceinline__ void conv_w_elem(const float* __restrict__ W,
                                            unsigned short* __restrict__ Wp,
                                            int K, int KP, int idx) {
    int n = idx / KP, k = idx - n * KP;
    float v = (k < K) ? W[(size_t)n * K + k] : 0.f;
    Wp[(size_t)n * KP + k] = __half_as_ushort(__float2half_rn(v));
}

__device__ __forceinline__ void pack_row8(const float v[8], unsigned short* out,
                                          int KP, int row, int kb) {
    float lo[8];
    #pragma unroll
    for (int e = 0; e < 8; e++)
        lo[e] = v[e] - __half2float(__float2half_rn(v[e]));
    uint4 hq = make_uint4(pack2h(v[0], v[1]), pack2h(v[2], v[3]), pack2h(v[4], v[5]), pack2h(v[6], v[7]));
    uint4 lq = make_uint4(pack2h(lo[0], lo[1]), pack2h(lo[2], lo[3]), pack2h(lo[4], lo[5]), pack2h(lo[6], lo[7]));
    int c = kb >> 4, c2 = (kb >> 3) & 1;
    char* rb_ = (char*)(out + (size_t)row * KP * 2) + c * 64 + c2 * 16;
    *(uint4*)(rb_)      = hq;
    *(uint4*)(rb_ + 32) = lq;
}

// ---------------- prep: weight packs + W_i A pack ----------------------------
#define NWI (512 * KP_WI)
#define NWH (512 * KP_WH)
#define NWO (512 * KP_WO)
#define NPK (NBOND * (KP_WI / 8))
#define NPREP (NWI + NWH + NWO + NPK)

__global__ void prep_kernel(const float* __restrict__ Wi, const float* __restrict__ Wh,
                            const float* __restrict__ Wo, const float* __restrict__ f_bonds) {
    int idx = blockIdx.x * blockDim.x + threadIdx.x;
    if (idx >= NPREP) return;
    if (idx < NWI) { conv_w_elem(Wi, g_Wi2, BF, KP_WI, idx); return; }
    idx -= NWI;
    if (idx < NWH) { conv_w_elem(Wh, g_Wh2, HID, KP_WH, idx); return; }
    idx -= NWH;
    if (idx < NWO) { conv_w_elem(Wo, g_Wo2, AF + HID, KP_WO, idx); return; }
    idx -= NWO;
    const int t8n = KP_WI / 8;
    int row = idx / t8n;
    int kb = (idx - row * t8n) * 8;
    float v[8];
    const float* r = f_bonds + (size_t)row * BF;
    #pragma unroll
    for (int e = 0; e < 8; e++)
        v[e] = (kb + e < BF) ? r[kb + e] : 0.f;
    pack_row8(v, g_pA, KP_WI, row, kb);
}

// ---------------- W_o A pack (concat f_atoms | amsg) -------------------------
__global__ void pack_awo_kernel(const float* __restrict__ f_atoms,
                                const float* __restrict__ amsg) {
    const int t8n = KP_WO / 8;
    int idx = blockIdx.x * blockDim.x + threadIdx.x;
    if (idx >= NA * t8n) return;
    int row = idx / t8n;
    int kb = (idx - row * t8n) * 8;
    float v[8];
    #pragma unroll
    for (int e = 0; e < 8; e++) {
        int k = kb + e;
        float x = 0.f;
        if (k < AF) x = f_atoms[(size_t)row * AF + k];
        else if (k < AF + HID) x = amsg[(size_t)row * HID + (k - AF)];
        v[e] = x;
    }
    pack_row8(v, g_pA, KP_WO, row, kb);
}

// ---------------- geometry ----------------------------------------------------
#define AROW 80                        // A smem row: 32h data + 8h pad
#define BROW 48                        // B smem row: 16h data + 8h pad
// packed GEMM (512 thr): 128M x 256N
#define A_STW (128 * AROW)             // 10240
#define B_STW (256 * BROW)             // 12288
#define SMEM_W (3 * (A_STW + B_STW))   // 67584
// fused GEMM (256 thr): 128M x 128N
#define A_STF (128 * AROW)             // 10240
#define B_STF (128 * BROW)             // 6144
#define FSM_BYTES (3 * (A_STF + B_STF))// 49152

// ------- packed-A GEMM (W_i / W_o): 512 thr, 16 warps 64x32, fp16 2-term ----
__global__ __launch_bounds__(512, 1)
void mma_gemm_kernel(const unsigned short* __restrict__ pA,
                     const unsigned short* __restrict__ Wp, int KP, int NC,
                     const float* __restrict__ bias,
                     float* __restrict__ out1, int relu1, int M) {
    extern __shared__ char dyn[];
    const uint32_t aBase = smem_u32(dyn);
    const uint32_t bBase = aBase + 3 * A_STW;

    const int tid = threadIdx.x;
    const int wid = tid >> 5, lane = tid & 31;
    const int bm = blockIdx.y * 128;
    const int bn = blockIdx.x * 256;
    const int wm = (wid >> 3) * 64;
    const int wn = (wid & 7) * 32;

    // A loader: (row 0..127, quarter 0..3) -> 16B of the 64B chunk row
    const int rA = tid >> 2, qA = tid & 3;
    const int gmL = bm + rA;
    const int okA = gmL < M;
    const int gmc = okA ? gmL : (M - 1);
    const char* gA = (const char*)(pA + (size_t)gmc * KP * 2) + qA * 16;
    const uint32_t sA = aBase + rA * AROW + qA * 16;
    // B loader: (row 0..255, half 0..1) -> 16B of the 32B chunk row
    const int rB = tid >> 1, hB = tid & 1;
    const char* gB = (const char*)(Wp + (size_t)(bn + rB) * KP) + hB * 16;
    const uint32_t sB = bBase + rB * BROW + hB * 16;

    float acc[4][4][4];
    #pragma unroll
    for (int i = 0; i < 4; i++)
        #pragma unroll
        for (int j = 0; j < 4; j++)
            #pragma unroll
            for (int e = 0; e < 4; e++) acc[i][j][e] = 0.f;

    auto prefetch = [&](int c, int s) {
        cp16(sA + s * A_STW, gA + (size_t)c * 64, okA);
        cp16(sB + s * B_STW, gB + (size_t)c * 32, 1);
        asm volatile("cp.async.commit_group;" ::: "memory");
    };

    const uint32_t aAddr = aBase + (wm + (lane & 15)) * AROW + (lane >> 4) * 16;
    const uint32_t bAddr = bBase + (wn + (lane & 7) + (lane >= 16 ? 8 : 0)) * BROW
                                 + ((lane >> 3) & 1) * 16;

    prefetch(0, 0);
    prefetch(1, 1);
    for (int c = 0; c < NC; c++) {
        int s = c % 3;
        if (c + 1 < NC) { asm volatile("cp.async.wait_group 1;" ::: "memory"); }
        else            { asm volatile("cp.async.wait_group 0;" ::: "memory"); }
        __syncthreads();
        if (c + 2 < NC) prefetch(c + 2, (c + 2) % 3);

        uint32_t aH[4][4], aL[4][4], bH[2][4];
        #pragma unroll
        for (int i = 0; i < 4; i++) {
            ldm_x4(aH[i], aAddr + s * A_STW + i * 16 * AROW);
            ldm_x4(aL[i], aAddr + s * A_STW + i * 16 * AROW + 32);
        }
        #pragma unroll
        for (int p = 0; p < 2; p++)
            ldm_x4(bH[p], bAddr + s * B_STW + p * 16 * BROW);
        #pragma unroll
        for (int i = 0; i < 4; i++)
            #pragma unroll
            for (int j = 0; j < 4; j++) {
                mma_f16(acc[i][j], aH[i], bH[j >> 1][(j & 1) * 2], bH[j >> 1][(j & 1) * 2 + 1]);
                mma_f16(acc[i][j], aL[i], bH[j >> 1][(j & 1) * 2], bH[j >> 1][(j & 1) * 2 + 1]);
            }
    }

    const int g = lane >> 2, tg = lane & 3;
    #pragma unroll
    for (int i = 0; i < 4; i++) {
        #pragma unroll
        for (int h = 0; h < 2; h++) {
            int gm = bm + wm + i * 16 + g + h * 8;
            if (gm >= M) continue;
            #pragma unroll
            for (int j = 0; j < 4; j++) {
                int gn = bn + wn + j * 8 + tg * 2;
                float v0 = acc[i][j][h * 2 + 0];
                float v1 = acc[i][j][h * 2 + 1];
                if (bias) {
                    float2 b = *(const float2*)(bias + gn);
                    v0 += b.x; v1 += b.y;
                }
                float2 o = relu1 ? make_float2(fmaxf(v0, 0.f), fmaxf(v1, 0.f))
                                 : make_float2(v0, v1);
                *(float2*)(out1 + (size_t)gm * HID + gn) = o;
            }
        }
    }
}

// ------- fused W_h GEMM: 256 thr, 128x128, 3-stage, fp16 2-term -------------
__global__ __launch_bounds__(256, 2)
void mma_gemm_fused_kernel(const float* __restrict__ amsg,
                           const float* __restrict__ msg,
                           const int* __restrict__ b2a,
                           const int* __restrict__ b2revb,
                           const unsigned short* __restrict__ Wp,
                           const float* __restrict__ inp,
                           float* __restrict__ out1, int reluMsg) {
    const int NC = KP_WH / 16;   // 32
    extern __shared__ char dyn[];
    const uint32_t aBase = smem_u32(dyn);
    const uint32_t bBase = aBase + 3 * A_STF;

    const int tid = threadIdx.x;
    const int wid = tid >> 5, lane = tid & 31;
    const int bm = blockIdx.y * 128;
    const int bn = blockIdx.x * 128;
    const int wm = (wid >> 2) * 64;
    const int wn = (wid & 3) * 32;

    const int rL = tid >> 1;
    const int c2 = tid & 1;
    const int gmL = bm + rL;
    const int okA = gmL < NBOND;
    const int gmc = okA ? gmL : (NBOND - 1);
    const int sa = b2a[gmc];
    const int rb = b2revb[gmc];
    const char* gU = (const char*)(amsg + (size_t)sa * HID) + c2 * 32;
    const char* gW = (const char*)(msg + (size_t)rb * HID) + c2 * 32;
    const char* gB = (const char*)(Wp + (size_t)(bn + rL) * KP_WH) + c2 * 16;
    const uint32_t sB = bBase + rL * BROW + c2 * 16;

    float acc[4][4][4];
    #pragma unroll
    for (int i = 0; i < 4; i++)
        #pragma unroll
        for (int j = 0; j < 4; j++)
            #pragma unroll
            for (int e = 0; e < 4; e++) acc[i][j][e] = 0.f;

    float4 u0, u1, w0, w1;
    auto loadA_issue = [&](int c) {
        const char* u = gU + (size_t)c * 64;
        const char* w = gW + (size_t)c * 64;
        u0 = *(const float4*)(u);
        u1 = *(const float4*)(u + 16);
        w0 = *(const float4*)(w);
        w1 = *(const float4*)(w + 16);
    };
    auto storeA = [&](int s) {
        float4 ww0 = w0, ww1 = w1;
        if (reluMsg) {
            ww0.x = fmaxf(ww0.x, 0.f); ww0.y = fmaxf(ww0.y, 0.f);
            ww0.z = fmaxf(ww0.z, 0.f); ww0.w = fmaxf(ww0.w, 0.f);
            ww1.x = fmaxf(ww1.x, 0.f); ww1.y = fmaxf(ww1.y, 0.f);
            ww1.z = fmaxf(ww1.z, 0.f); ww1.w = fmaxf(ww1.w, 0.f);
        }
        float v[8];
        v[0] = u0.x - ww0.x; v[1] = u0.y - ww0.y; v[2] = u0.z - ww0.z; v[3] = u0.w - ww0.w;
        v[4] = u1.x - ww1.x; v[5] = u1.y - ww1.y; v[6] = u1.z - ww1.z; v[7] = u1.w - ww1.w;
        float lo[8];
        #pragma unroll
        for (int e = 0; e < 8; e++)
            lo[e] = v[e] - __half2float(__float2half_rn(v[e]));
        uint4 hq = make_uint4(pack2h(v[0], v[1]), pack2h(v[2], v[3]), pack2h(v[4], v[5]), pack2h(v[6], v[7]));
        uint4 lq = make_uint4(pack2h(lo[0], lo[1]), pack2h(lo[2], lo[3]), pack2h(lo[4], lo[5]), pack2h(lo[6], lo[7]));
        char* ar = dyn + s * A_STF + rL * AROW;
        *(uint4*)(ar + c2 * 16)      = hq;
        *(uint4*)(ar + 32 + c2 * 16) = lq;
    };
    auto prefetchB = [&](int c, int s) {
        cp16(sB + s * B_STF, gB + (size_t)c * 32, 1);
        asm volatile("cp.async.commit_group;" ::: "memory");
    };

    const uint32_t aAddr = aBase + (wm + (lane & 15)) * AROW + (lane >> 4) * 16;
    const uint32_t bAddr = bBase + (wn + (lane & 7) + (lane >= 16 ? 8 : 0)) * BROW
                                 + ((lane >> 3) & 1) * 16;

    loadA_issue(0); storeA(0); prefetchB(0, 0);
    loadA_issue(1); storeA(1); prefetchB(1, 1);

    int buf = 0;
    #pragma unroll 1
    for (int c = 0; c < NC; c++) {
        if (c + 1 < NC) { asm volatile("cp.async.wait_group 1;" ::: "memory"); }
        else            { asm volatile("cp.async.wait_group 0;" ::: "memory"); }
        __syncthreads();

        int nb = buf + 2; if (nb >= 3) nb -= 3;
        if (c + 2 < NC) loadA_issue(c + 2);

        uint32_t af[4][4], bH[2][4];
        #pragma unroll
        for (int p = 0; p < 2; p++)
            ldm_x4(bH[p], bAddr + buf * B_STF + p * 16 * BROW);
        #pragma unroll
        for (int i = 0; i < 4; i++)
            ldm_x4(af[i], aAddr + buf * A_STF + i * 16 * AROW);       // aH
        #pragma unroll
        for (int i = 0; i < 4; i++)
            #pragma unroll
            for (int j = 0; j < 4; j++)
                mma_f16(acc[i][j], af[i], bH[j >> 1][(j & 1) * 2], bH[j >> 1][(j & 1) * 2 + 1]);
        #pragma unroll
        for (int i = 0; i < 4; i++)
            ldm_x4(af[i], aAddr + buf * A_STF + i * 16 * AROW + 32);  // aL
        #pragma unroll
        for (int i = 0; i < 4; i++)
            #pragma unroll
            for (int j = 0; j < 4; j++)
                mma_f16(acc[i][j], af[i], bH[j >> 1][(j & 1) * 2], bH[j >> 1][(j & 1) * 2 + 1]);

        if (c + 2 < NC) { storeA(nb); prefetchB(c + 2, nb); }
        buf++; if (buf == 3) buf = 0;
    }

    const int g = lane >> 2, tg = lane & 3;
    #pragma unroll
    for (int i = 0; i < 4; i++) {
        #pragma unroll
        for (int h = 0; h < 2; h++) {
            int gm = bm + wm + i * 16 + g + h * 8;
            if (gm >= NBOND) continue;
            #pragma unroll
            for (int j = 0; j < 4; j++) {
                int gn = bn + wn + j * 8 + tg * 2;
                float2 a = *(const float2*)(inp + (size_t)gm * HID + gn);
                float v0 = acc[i][j][h * 2 + 0] + a.x;
                float v1 = acc[i][j][h * 2 + 1] + a.y;
                *(float2*)(out1 + (size_t)gm * HID + gn) =
                    make_float2(fmaxf(v0, 0.f), fmaxf(v1, 0.f));
            }
        }
    }
}

// ----- gather: warp per atom; lane covers float4 lane, +32, +64, +96 ---------
__global__ void gather_sum_kernel(const float* __restrict__ msg,
                                  float* __restrict__ amsg, int reluSrc) {
    int gidx = blockIdx.x * blockDim.x + threadIdx.x;
    int a = gidx >> 5;
    int lane = gidx & 31;
    if (a >= NA) return;
    int bidx[MAXNB];
    #pragma unroll
    for (int j = 0; j < MAXNB; j++) bidx[j] = g_a2b[a * MAXNB + j];
    float4 acc[4];
    #pragma unroll
    for (int q = 0; q < 4; q++) acc[q] = make_float4(0.f, 0.f, 0.f, 0.f);
    #pragma unroll
    for (int j = 0; j < MAXNB; j++) {
        const float4* row = (const float4*)(msg + (size_t)bidx[j] * HID);
        #pragma unroll
        for (int q = 0; q < 4; q++) {
            float4 v = row[lane + q * 32];
            if (reluSrc) {
                v.x = fmaxf(v.x, 0.f); v.y = fmaxf(v.y, 0.f);
                v.z = fmaxf(v.z, 0.f); v.w = fmaxf(v.w, 0.f);
            }
            acc[q].x += v.x; acc[q].y += v.y; acc[q].z += v.z; acc[q].w += v.w;
        }
    }
    float4* dst = (float4*)(amsg + (size_t)a * HID);
    #pragma unroll
    for (int q = 0; q < 4; q++) dst[lane + q * 32] = acc[q];
}

// ---------------- pooling -----------------------------------------------------
__global__ void pool_zero_kernel() {
    int i = blockIdx.x * blockDim.x + threadIdx.x;
    if (i < NM * HID) g_sums[i] = 0.f;
    if (i < NM) g_cnt[i] = 0.f;
}
__global__ void pool_sum_kernel(const float* __restrict__ ah) {
    int idx = blockIdx.x * blockDim.x + threadIdx.x;
    const int h4 = HID / 4;
    if (idx >= NA * h4) return;
    int a = idx / h4;
    int h = (idx - a * h4) * 4;
    int m = g_mol[a];
    float4 v = *(const float4*)(ah + (size_t)a * HID + h);
    float* dst = g_sums + (size_t)m * HID + h;
    atomicAdd(dst + 0, v.x);
    atomicAdd(dst + 1, v.y);
    atomicAdd(dst + 2, v.z);
    atomicAdd(dst + 3, v.w);
    if (h == 0) atomicAdd(&g_cnt[m], 1.f);
}
__global__ void finalize_kernel(float* __restrict__ out) {
    int i = blockIdx.x * blockDim.x + threadIdx.x;
    if (i >= NM * HID) return;
    float c = g_cnt[i / HID];
    out[i] = g_sums[i] / fmaxf(c, 1.f);
}

// ---------------- launch ------------------------------------------------------
extern "C" void kernel_launch(void* const* d_in, const int* in_sizes, int n_in,
                              void* d_out, int out_size) {
    const float* f_atoms = (const float*)d_in[0];
    const float* f_bonds = (const float*)d_in[1];
    const float* W_i     = (const float*)d_in[2];
    const float* W_h     = (const float*)d_in[3];
    const float* W_o     = (const float*)d_in[4];
    const float* b_o     = (const float*)d_in[5];
    const void*  a2b     = d_in[6];
    const void*  b2a     = d_in[7];
    const void*  b2revb  = d_in[8];
    const void*  mol     = d_in[9];
    float* out = (float*)d_out;

    int* d_b2a;    cudaGetSymbolAddress((void**)&d_b2a, g_b2a);
    int* d_b2revb; cudaGetSymbolAddress((void**)&d_b2revb, g_b2revb);
    float* d_inp;  cudaGetSymbolAddress((void**)&d_inp, g_inp);
    float* d_msgA; cudaGetSymbolAddress((void**)&d_msgA, g_msgA);
    float* d_msgB; cudaGetSymbolAddress((void**)&d_msgB, g_msgB);
    float* d_amsg; cudaGetSymbolAddress((void**)&d_amsg, g_amsg);
    float* d_ah;   cudaGetSymbolAddress((void**)&d_ah, g_ah);
    unsigned short* d_Wi2; cudaGetSymbolAddress((void**)&d_Wi2, g_Wi2);
    unsigned short* d_Wh2; cudaGetSymbolAddress((void**)&d_Wh2, g_Wh2);
    unsigned short* d_Wo2; cudaGetSymbolAddress((void**)&d_Wo2, g_Wo2);
    unsigned short* d_pA;  cudaGetSymbolAddress((void**)&d_pA, g_pA);

    static int init_done = 0;
    if (!init_done) {
        cudaFuncSetAttribute(mma_gemm_kernel,
                             cudaFuncAttributeMaxDynamicSharedMemorySize, SMEM_W);
        cudaFuncSetAttribute(mma_gemm_fused_kernel,
                             cudaFuncAttributeMaxDynamicSharedMemorySize, FSM_BYTES);
        init_done = 1;
    }

    const int mt_b = (NBOND + 127) / 128;     // 938
    const int mt_a = (NA + 127) / 128;        // 469
    const int gthreads = 256;
    const int gblocks_g = (NA * 32 + gthreads - 1) / gthreads;
    const int gblocks_p = (NA * (HID / 4) + gthreads - 1) / gthreads;

    // setup
    scan_all_kernel<<<(NTOT + 255) / 256, 256>>>(
        (const unsigned*)a2b, (const unsigned*)b2a, (const unsigned*)b2revb, (const unsigned*)mol);
    convert_all_kernel<<<(NTOT + 255) / 256, 256>>>(a2b, b2a, b2revb, mol);
    prep_kernel<<<(NPREP + 255) / 256, 256>>>(W_i, W_h, W_o, f_bonds);

    // inp = f_bonds @ W_i^T (pre-relu; msg0 virtual)
    mma_gemm_kernel<<<dim3(2, mt_b), 512, SMEM_W>>>(
        d_pA, d_Wi2, KP_WI, KP_WI / 16, nullptr, d_inp, 0, NBOND);

    // message passing; it0 applies relu on read
    gather_sum_kernel<<<gblocks_g, gthreads>>>(d_inp, d_amsg, 1);
    mma_gemm_fused_kernel<<<dim3(4, mt_b), 256, FSM_BYTES>>>(
        d_amsg, d_inp, d_b2a, d_b2revb, d_Wh2, d_inp, d_msgA, 1);

    float* cur = d_msgA;
    float* alt = d_msgB;
    for (int it = 1; it < 4; it++) {
        gather_sum_kernel<<<gblocks_g, gthreads>>>(cur, d_amsg, 0);
        mma_gemm_fused_kernel<<<dim3(4, mt_b), 256, FSM_BYTES>>>(
            d_amsg, cur, d_b2a, d_b2revb, d_Wh2, d_inp, alt, 0);
        float* t = cur; cur = alt; alt = t;
    }

    // final gather + W_o GEMM
    gather_sum_kernel<<<gblocks_g, gthreads>>>(cur, d_amsg, 0);
    pack_awo_kernel<<<(NA * (KP_WO / 8) + 255) / 256, 256>>>(f_atoms, d_amsg);
    mma_gemm_kernel<<<dim3(2, mt_a), 512, SMEM_W>>>(
        d_pA, d_Wo2, KP_WO, KP_WO / 16, b_o, d_ah, 1, NA);

    // pooling
    pool_zero_kernel<<<(NM * HID + 255) / 256, 256>>>();
    pool_sum_kernel<<<gblocks_p, gthreads>>>(d_ah);
    finalize_kernel<<<(NM * HID + 255) / 256, 256>>>(out);
}